// round 4
// baseline (speedup 1.0000x reference)
#include <cuda_runtime.h>
#include <cstdint>

// ---------------------------------------------------------------------------
// FeatureAlign: offset conv (1x1) -> deformable conv v1 -> GroupNorm -> ReLU
// sm_100 plain target (no tcgen05/TMA): tf32 mma.sync, cp.async.
//
// FUSED design (this round): the bilinear sampling is produced inside the
// GEMM's B-tile producer — no 302 MB scratch tensor.
//   K permuted: k' = k2*256 + c  (each BK=16 slice = one (g,k2), 16 channels)
//   Phase A': prep w_deform -> tf32 fragment-ordered g_A with k' permutation
//   Phase B : fused sample+GEMM, BM=256,BN=128,BK=16, 8 warps, 3-stage A
//             cp.async pipeline, B computed in-regs (gather overlapped w/ mma)
//   Phase C : GroupNorm stats + normalize/ReLU in place on d_out
// ---------------------------------------------------------------------------

#define Bn 8
#define Cn 256
#define On 256
#define Hn 64
#define Wn 64
#define HW 4096
#define DG 4
#define CG 64
#define K2 9
#define KDIM 2304
#define NDIM 32768

#define BM 256
#define BN 128
#define BK 16
#define ITERS (KDIM / BK)        // 144
#define NK8 (KDIM / 8)           // 288

__device__ float g_A[(size_t)NK8 * 16 * 32 * 4];  // fragment-ordered weights
__device__ float g_stats[256 * 2];

// ------------------------------ helpers ------------------------------------
__device__ __forceinline__ uint32_t smem_u32(const void* p) {
    uint32_t a;
    asm("{ .reg .u64 t; cvta.to.shared.u64 t, %1; cvt.u32.u64 %0, t; }" : "=r"(a) : "l"(p));
    return a;
}
__device__ __forceinline__ float to_tf32(float v) {
    uint32_t r;
    asm("cvt.rna.tf32.f32 %0, %1;" : "=r"(r) : "f"(v));
    return __uint_as_float(r);
}
#define CP16(dst_u32, src_ptr) \
    asm volatile("cp.async.cg.shared.global [%0], [%1], 16;" :: "r"(dst_u32), "l"(src_ptr) : "memory")
#define CP_COMMIT() asm volatile("cp.async.commit_group;" ::: "memory")
#define CP_WAIT2()  asm volatile("cp.async.wait_group 2;" ::: "memory")

__device__ __forceinline__ void mma_tf32(float* c, const uint32_t* a, const uint32_t* b) {
    asm volatile(
        "mma.sync.aligned.m16n8k8.row.col.f32.tf32.tf32.f32 "
        "{%0,%1,%2,%3}, {%4,%5,%6,%7}, {%8,%9}, {%0,%1,%2,%3};"
        : "+f"(c[0]), "+f"(c[1]), "+f"(c[2]), "+f"(c[3])
        : "r"(a[0]), "r"(a[1]), "r"(a[2]), "r"(a[3]), "r"(b[0]), "r"(b[1]));
}

// ---------------------------------------------------------------------------
// Phase A': weight prep -> tf32, mma fragment order, k'-permuted
// k' = k2*256 + c  ->  source column = c*9 + k2
// ---------------------------------------------------------------------------
__global__ void prep_a_kernel(const float* __restrict__ wd)   // [256][2304]
{
    const int idx = blockIdx.x * 256 + threadIdx.x;           // < 288*16*32
    const int lane = idx & 31;
    const int mt = (idx >> 5) & 15;
    const int s = idx >> 9;
    const int m0 = mt * 16 + (lane >> 2);
    const int kp0 = s * 8 + (lane & 3);
    const int kp1 = kp0 + 4;
    const int src0 = (kp0 & 255) * 9 + (kp0 >> 8);
    const int src1 = (kp1 & 255) * 9 + (kp1 >> 8);
    float4 v;
    v.x = to_tf32(wd[(size_t)m0 * KDIM + src0]);
    v.y = to_tf32(wd[(size_t)(m0 + 8) * KDIM + src0]);
    v.z = to_tf32(wd[(size_t)m0 * KDIM + src1]);
    v.w = to_tf32(wd[(size_t)(m0 + 8) * KDIM + src1]);
    ((float4*)g_A)[idx] = v;
}

// ---------------------------------------------------------------------------
// Phase B: fused sample + tf32 mma.sync GEMM
// grid = 256 (one 128-pixel n-tile each, fixed b), block = 256 (8 warps)
// smem: A stages 3x4096f | B stages 3x2176f | wtab 4608 float4 | itab 4608 u32
// ---------------------------------------------------------------------------
#define A_ST_F 4096
#define B_ST_F 2176
#define WTAB_F 18432      // 4608 * 4 floats
#define GEMM_SMEM ((3 * A_ST_F + 3 * B_ST_F + WTAB_F + 4608) * 4)

__global__ void __launch_bounds__(256, 1) gemm_kernel(const float* __restrict__ x,
                                                      const float* __restrict__ x_off,
                                                      const float* __restrict__ w_offset,
                                                      float* __restrict__ out)
{
    extern __shared__ float smemf[];
    float* sBf = smemf + 3 * A_ST_F;
    float4* wtab = (float4*)(smemf + 3 * A_ST_F + 3 * B_ST_F);
    uint32_t* itab = (uint32_t*)(smemf + 3 * A_ST_F + 3 * B_ST_F + WTAB_F);
    const uint32_t sA_u = smem_u32(smemf);

    const int tid = threadIdx.x;
    const int lane = tid & 31;
    const int wid = tid >> 5;
    const int n0 = blockIdx.x * BN;
    const int b = n0 >> 12;
    const int hwbase = n0 & 4095;

    // ---- prologue 1: build bilinear tables for all (g,k2) slices ----------
    for (int e = tid; e < 4608; e += 256) {
        const int pix = e & 127;
        const int gk = e >> 7;            // g*9 + k2
        const int g = gk / 9;
        const int k2 = gk - g * 9;
        const int hw = hwbase + pix;
        const int h = hw >> 6;
        const int w = hw & 63;

        const float* xo = x_off + (size_t)b * 4 * HW + hw;
        const float o0 = __ldg(xo), o1 = __ldg(xo + HW), o2 = __ldg(xo + 2 * HW), o3 = __ldg(xo + 3 * HW);
        const float* wo = w_offset + (g * 18 + k2 * 2) * 4;
        const float offy = wo[0] * o0 + wo[1] * o1 + wo[2] * o2 + wo[3] * o3;
        const float offx = wo[4] * o0 + wo[5] * o1 + wo[6] * o2 + wo[7] * o3;

        const float py = (float)h + (float)(k2 / 3 - 1) + offy;
        const float px = (float)w + (float)(k2 % 3 - 1) + offx;
        const float fy = floorf(py), fx = floorf(px);
        const int y0 = (int)fy, x0i = (int)fx;
        const float wy = py - fy, wx = px - fx;

        float w00 = (1.f - wy) * (1.f - wx);
        float w01 = (1.f - wy) * wx;
        float w10 = wy * (1.f - wx);
        float w11 = wy * wx;
        const bool vy0 = (y0 >= 0) & (y0 < Hn);
        const bool vy1 = (y0 + 1 >= 0) & (y0 + 1 < Hn);
        const bool vx0 = (x0i >= 0) & (x0i < Wn);
        const bool vx1 = (x0i + 1 >= 0) & (x0i + 1 < Wn);
        w00 = (vy0 & vx0) ? w00 : 0.f;
        w01 = (vy0 & vx1) ? w01 : 0.f;
        w10 = (vy1 & vx0) ? w10 : 0.f;
        w11 = (vy1 & vx1) ? w11 : 0.f;

        const int yc0 = min(max(y0, 0), Hn - 1);
        const int yc1 = min(max(y0 + 1, 0), Hn - 1);
        const int xc0 = min(max(x0i, 0), Wn - 1);
        const int xc1 = min(max(x0i + 1, 0), Wn - 1);
        wtab[e] = make_float4(w00, w01, w10, w11);
        itab[e] = (uint32_t)(yc0 * 64 + xc0) | ((uint32_t)(yc1 * 64 + xc1) << 12);
    }

    // ---- prologue 2: A cp.async stages 0..2 -------------------------------
    auto load_a = [&](int iter, int s) {
        const float4* srcA = (const float4*)g_A + (size_t)iter * 1024;
        const uint32_t dA = sA_u + (uint32_t)s * (A_ST_F * 4);
#pragma unroll
        for (int j = 0; j < 4; j++) {
            const int idx = j * 256 + tid;
            CP16(dA + idx * 16, srcA + idx);
        }
        CP_COMMIT();
    };
    load_a(0, 0);
    load_a(1, 1);
    load_a(2, 2);

    // ---- B producer pieces ------------------------------------------------
    const int pix = tid & 127;
    const int halfc = tid >> 7;           // 0/1: channel parity within slice
    const float* xb = x + ((size_t)b * Cn << 12);

    float4 wv;
    int i00, i01, i10, i11;
    const float* xc_base;
    auto setup_iter = [&](int iter) {
        const int kp = iter * BK;
        const int k2 = kp >> 8;
        const int c0 = kp & 255;
        const int g = c0 >> 6;
        const int e = (g * 9 + k2) * 128 + pix;
        wv = wtab[e];
        const uint32_t idx = itab[e];
        i00 = idx & 4095;
        i11 = (idx >> 12) & 4095;
        i01 = (i00 & ~63) | (i11 & 63);
        i10 = (i11 & ~63) | (i00 & 63);
        xc_base = xb + ((size_t)(c0 + halfc) << 12);
    };
    float tv[8][4];
    auto gather = [&]() {
#pragma unroll
        for (int j = 0; j < 8; j++) {
            const float* xc = xc_base + ((size_t)j << 13);   // +2 channels
            tv[j][0] = __ldg(xc + i00);
            tv[j][1] = __ldg(xc + i01);
            tv[j][2] = __ldg(xc + i10);
            tv[j][3] = __ldg(xc + i11);
        }
    };
    auto emit = [&](int s) {
        float* bst = sBf + s * B_ST_F;
#pragma unroll
        for (int j = 0; j < 8; j++) {
            float v = wv.x * tv[j][0] + wv.y * tv[j][1]
                    + wv.z * tv[j][2] + wv.w * tv[j][3];
            bst[(halfc + 2 * j) * 136 + pix] = to_tf32(v);
        }
    };

    __syncthreads();              // tables visible
    setup_iter(0);
    gather();
    emit(0);                      // B(0) into buf 0

    // ---- mainloop ---------------------------------------------------------
    const int g4 = lane >> 2;
    const int l4 = lane & 3;
    const int wm = wid & 3;
    const int wn = wid >> 2;

    float acc[4][8][4];
#pragma unroll
    for (int i = 0; i < 4; i++)
#pragma unroll
        for (int j = 0; j < 8; j++)
#pragma unroll
            for (int q = 0; q < 4; q++) acc[i][j][q] = 0.f;

    for (int iter = 0; iter < ITERS; iter++) {
        const int s = iter % 3;
        const bool more = (iter + 1 < ITERS);
        if (more) { setup_iter(iter + 1); gather(); }   // overlap with mma

        CP_WAIT2();
        __syncthreads();          // A(iter) + B(iter) ready

        const uint32_t aS = sA_u + (uint32_t)s * (A_ST_F * 4);
        const float* bS = sBf + s * B_ST_F;
#pragma unroll
        for (int k8 = 0; k8 < 2; k8++) {
            uint32_t af[4][4];
#pragma unroll
            for (int i = 0; i < 4; i++) {
                const uint32_t addr = aS + (((k8 * 16 + wm * 4 + i) * 32 + lane) << 4);
                asm volatile("ld.shared.v4.b32 {%0,%1,%2,%3}, [%4];"
                             : "=r"(af[i][0]), "=r"(af[i][1]), "=r"(af[i][2]), "=r"(af[i][3])
                             : "r"(addr));
            }
            uint32_t bf[8][2];
            const int r0 = k8 * 8 + l4;
            const float* bp = bS + wn * 64 + g4;
#pragma unroll
            for (int j = 0; j < 8; j++) {
                bf[j][0] = __float_as_uint(bp[r0 * 136 + j * 8]);
                bf[j][1] = __float_as_uint(bp[(r0 + 4) * 136 + j * 8]);
            }
#pragma unroll
            for (int i = 0; i < 4; i++)
#pragma unroll
                for (int j = 0; j < 8; j++)
                    mma_tf32(acc[i][j], af[i], bf[j]);
        }
        __syncthreads();          // everyone done reading stage s

        if (more) emit((iter + 1) % 3);
        if (iter + 3 < ITERS) load_a(iter + 3, s);
        else CP_COMMIT();         // keep wait_group accounting consistent
    }

    // ---- epilogue: C -> out[b][o][hw] -------------------------------------
    const int hw0 = hwbase + wn * 64 + l4 * 2;
#pragma unroll
    for (int i = 0; i < 4; i++) {
        const int o0 = wm * 64 + i * 16 + g4;
        float* p0 = out + (((size_t)b * On + o0) << 12) + hw0;
        float* p1 = out + (((size_t)b * On + o0 + 8) << 12) + hw0;
#pragma unroll
        for (int j = 0; j < 8; j++) {
            *(float2*)(p0 + j * 8) = make_float2(acc[i][j][0], acc[i][j][1]);
            *(float2*)(p1 + j * 8) = make_float2(acc[i][j][2], acc[i][j][3]);
        }
    }
}

// ---------------------------------------------------------------------------
// Phase C1: GroupNorm statistics (one block per (b, group), contiguous 32768)
// ---------------------------------------------------------------------------
__global__ void gn_stats_kernel(const float* __restrict__ y)
{
    const int bgp = blockIdx.x;
    const float* p = y + (size_t)bgp * 32768;
    const int tid = threadIdx.x;

    float s = 0.f, sq = 0.f;
    for (int i = tid * 4; i < 32768; i += 256 * 4) {
        float4 v = *(const float4*)(p + i);
        s  += v.x + v.y + v.z + v.w;
        sq += v.x * v.x + v.y * v.y + v.z * v.z + v.w * v.w;
    }

    __shared__ float ss[256], ssq[256];
    ss[tid] = s; ssq[tid] = sq;
    __syncthreads();
    for (int st = 128; st > 0; st >>= 1) {
        if (tid < st) { ss[tid] += ss[tid + st]; ssq[tid] += ssq[tid + st]; }
        __syncthreads();
    }
    if (tid == 0) {
        const float inv = 1.f / 32768.f;
        const float mu = ss[0] * inv;
        const float var = ssq[0] * inv - mu * mu;
        g_stats[bgp * 2 + 0] = mu;
        g_stats[bgp * 2 + 1] = rsqrtf(var + 1e-5f);
    }
}

// ---------------------------------------------------------------------------
// Phase C2: normalize + affine + ReLU (in place)
// ---------------------------------------------------------------------------
__global__ void gn_apply_kernel(float* __restrict__ y,
                                const float* __restrict__ gamma,
                                const float* __restrict__ beta)
{
    const int i = blockIdx.x * blockDim.x + threadIdx.x;
    const int e = i * 4;
    if (e >= Bn * On * HW) return;
    const int bgp = e >> 15;
    const int o = (e >> 12) & 255;
    const float mu = g_stats[bgp * 2 + 0];
    const float rs = g_stats[bgp * 2 + 1];
    const float ga = gamma[o] * rs;
    const float be = beta[o] - mu * ga;
    float4 v = *(float4*)(y + e);
    v.x = fmaxf(fmaf(v.x, ga, be), 0.f);
    v.y = fmaxf(fmaf(v.y, ga, be), 0.f);
    v.z = fmaxf(fmaf(v.z, ga, be), 0.f);
    v.w = fmaxf(fmaf(v.w, ga, be), 0.f);
    *(float4*)(y + e) = v;
}

// ---------------------------------------------------------------------------
extern "C" void kernel_launch(void* const* d_in, const int* in_sizes, int n_in,
                              void* d_out, int out_size)
{
    const float* x        = (const float*)d_in[0];
    const float* x_off    = (const float*)d_in[1];
    const float* w_offset = (const float*)d_in[2];
    const float* w_deform = (const float*)d_in[3];
    const float* gamma    = (const float*)d_in[4];
    const float* beta     = (const float*)d_in[5];
    float* out = (float*)d_out;

    (void)in_sizes; (void)n_in; (void)out_size;

    cudaFuncSetAttribute(gemm_kernel, cudaFuncAttributeMaxDynamicSharedMemorySize, GEMM_SMEM);

    prep_a_kernel<<<NK8 * 16 * 32 / 256, 256>>>(w_deform);
    gemm_kernel<<<NDIM / BN, 256, GEMM_SMEM>>>(x, x_off, w_offset, out);
    gn_stats_kernel<<<256, 256>>>(out);
    gn_apply_kernel<<<(Bn * On * HW / 4 + 255) / 256, 256>>>(out, gamma, beta);
}

// round 5
// speedup vs baseline: 1.0082x; 1.0082x over previous
#include <cuda_runtime.h>
#include <cstdint>

// ---------------------------------------------------------------------------
// FeatureAlign: offset conv (1x1) -> deformable conv v1 -> GroupNorm -> ReLU
// sm_100 plain target: tf32 mma.sync + cp.async + mbarrier (no tcgen05/TMA).
//
// Warp-specialized fused kernel:
//   - 8 consumer warps: 3-stage tf32 mma.sync GEMM (BM=256,BN=128,BK=16)
//   - 2 producer warps: bilinear gather + emit B tiles into smem stages
//   - K permuted: k' = k2*256 + c  (each BK=16 slice = one (g,k2), 16 chans)
//   - prep_off: offsets (1x1 conv) precomputed to a small global table
//   - prep_a:   w_deform -> tf32 fragment-ordered, k'-permuted
//   - GroupNorm stats + apply/ReLU in place on d_out
// ---------------------------------------------------------------------------

#define Bn 8
#define Cn 256
#define On 256
#define Hn 64
#define Wn 64
#define HW 4096
#define DG 4
#define CG 64
#define K2 9
#define KDIM 2304
#define NDIM 32768

#define BM 256
#define BN 128
#define BK 16
#define ITERS (KDIM / BK)        // 144
#define NK8 (KDIM / 8)           // 288

__device__ float g_A[(size_t)NK8 * 16 * 32 * 4];  // fragment-ordered weights
__device__ float2 g_off[(size_t)Bn * 36 * HW];    // [b][g*9+k2][hw] offsets (9.4 MB)
__device__ float g_stats[256 * 2];

// ------------------------------ helpers ------------------------------------
__device__ __forceinline__ uint32_t smem_u32(const void* p) {
    uint32_t a;
    asm("{ .reg .u64 t; cvta.to.shared.u64 t, %1; cvt.u32.u64 %0, t; }" : "=r"(a) : "l"(p));
    return a;
}
__device__ __forceinline__ float to_tf32(float v) {
    uint32_t r;
    asm("cvt.rna.tf32.f32 %0, %1;" : "=r"(r) : "f"(v));
    return __uint_as_float(r);
}
#define CP16(dst_u32, src_ptr) \
    asm volatile("cp.async.cg.shared.global [%0], [%1], 16;" :: "r"(dst_u32), "l"(src_ptr) : "memory")
#define CP_COMMIT() asm volatile("cp.async.commit_group;" ::: "memory")
#define CP_WAIT2()  asm volatile("cp.async.wait_group 2;" ::: "memory")

#define MBAR_INIT(addr, cnt) \
    asm volatile("mbarrier.init.shared.b64 [%0], %1;" :: "r"(addr), "r"(cnt) : "memory")
#define MBAR_ARRIVE(addr) \
    asm volatile("mbarrier.arrive.shared.b64 _, [%0];" :: "r"(addr) : "memory")

__device__ __forceinline__ void mbar_wait(uint32_t mbar, uint32_t parity) {
    asm volatile(
        "{\n\t"
        ".reg .pred P;\n\t"
        "WL_%=:\n\t"
        "mbarrier.try_wait.parity.acquire.cta.shared::cta.b64 P, [%0], %1, 0x989680;\n\t"
        "@P bra.uni WD_%=;\n\t"
        "bra.uni WL_%=;\n\t"
        "WD_%=:\n\t"
        "}"
        :: "r"(mbar), "r"(parity) : "memory");
}

#define BAR_CONS() asm volatile("bar.sync 1, 256;" ::: "memory")

__device__ __forceinline__ void mma_tf32(float* c, const uint32_t* a, const uint32_t* b) {
    asm volatile(
        "mma.sync.aligned.m16n8k8.row.col.f32.tf32.tf32.f32 "
        "{%0,%1,%2,%3}, {%4,%5,%6,%7}, {%8,%9}, {%0,%1,%2,%3};"
        : "+f"(c[0]), "+f"(c[1]), "+f"(c[2]), "+f"(c[3])
        : "r"(a[0]), "r"(a[1]), "r"(a[2]), "r"(a[3]), "r"(b[0]), "r"(b[1]));
}

// ---------------------------------------------------------------------------
// prep_off: offset 1x1 conv -> g_off[b][g*9+k2][hw] = (offy, offx)
// ---------------------------------------------------------------------------
__global__ void prep_off_kernel(const float* __restrict__ x_off,
                                const float* __restrict__ w_offset)
{
    const int idx = blockIdx.x * 256 + threadIdx.x;    // < 1179648
    const int hw = idx & 4095;
    const int t = idx >> 12;                           // b*36 + gk
    const int b = t / 36;
    const int gk = t - b * 36;
    const int g = gk / 9;
    const int k2 = gk - g * 9;

    const float* xo = x_off + (size_t)b * 4 * HW + hw;
    const float o0 = __ldg(xo), o1 = __ldg(xo + HW);
    const float o2 = __ldg(xo + 2 * HW), o3 = __ldg(xo + 3 * HW);
    const float* wo = w_offset + (g * 18 + k2 * 2) * 4;
    const float offy = wo[0] * o0 + wo[1] * o1 + wo[2] * o2 + wo[3] * o3;
    const float offx = wo[4] * o0 + wo[5] * o1 + wo[6] * o2 + wo[7] * o3;
    g_off[idx] = make_float2(offy, offx);
}

// ---------------------------------------------------------------------------
// prep_a: weights -> tf32, mma fragment order, k'-permuted (k'=k2*256+c)
// ---------------------------------------------------------------------------
__global__ void prep_a_kernel(const float* __restrict__ wd)   // [256][2304]
{
    const int idx = blockIdx.x * 256 + threadIdx.x;           // < 288*16*32
    const int lane = idx & 31;
    const int mt = (idx >> 5) & 15;
    const int s = idx >> 9;
    const int m0 = mt * 16 + (lane >> 2);
    const int kp0 = s * 8 + (lane & 3);
    const int kp1 = kp0 + 4;
    const int src0 = (kp0 & 255) * 9 + (kp0 >> 8);
    const int src1 = (kp1 & 255) * 9 + (kp1 >> 8);
    float4 v;
    v.x = to_tf32(wd[(size_t)m0 * KDIM + src0]);
    v.y = to_tf32(wd[(size_t)(m0 + 8) * KDIM + src0]);
    v.z = to_tf32(wd[(size_t)m0 * KDIM + src1]);
    v.w = to_tf32(wd[(size_t)(m0 + 8) * KDIM + src1]);
    ((float4*)g_A)[idx] = v;
}

// ---------------------------------------------------------------------------
// Fused sample+GEMM, warp-specialized.
// grid = 256 (n-tiles), block = 320: tid<256 consumers, tid>=256 producers.
// smem: A stages 3x4096f | B stages 3x2176f ; mbarriers static.
// ---------------------------------------------------------------------------
#define A_ST_F 4096
#define B_ST_F 2176
#define GEMM_SMEM ((3 * A_ST_F + 3 * B_ST_F) * 4)

__global__ void __launch_bounds__(320, 1) gemm_kernel(const float* __restrict__ x,
                                                      float* __restrict__ out)
{
    extern __shared__ float smemf[];
    __shared__ uint64_t mbar[6];       // full[0..2], empty[3..5]
    float* sBf = smemf + 3 * A_ST_F;
    const uint32_t sA_u = smem_u32(smemf);
    const uint32_t fullb = smem_u32(&mbar[0]);
    const uint32_t emptyb = smem_u32(&mbar[3]);

    const int tid = threadIdx.x;
    const int lane = tid & 31;
    const int n0 = blockIdx.x * BN;
    const int b = n0 >> 12;
    const int hwbase = n0 & 4095;

    if (tid == 0) {
#pragma unroll
        for (int s = 0; s < 3; s++) {
            MBAR_INIT(fullb + s * 8, 2u);    // 2 producer warps
            MBAR_INIT(emptyb + s * 8, 8u);   // 8 consumer warps
        }
    }
    __syncthreads();

    if (tid >= 256) {
        // =================== PRODUCER (2 warps, 64 threads) ================
        const int ptid = tid - 256;                 // 0..63
        const float* xb = x + ((size_t)b * Cn << 12);
        int eph[3] = {1, 1, 1};

        for (int iter = 0; iter < ITERS; iter++) {
            const int s = iter % 3;
            mbar_wait(emptyb + s * 8, (uint32_t)eph[s]); eph[s] ^= 1;

            const int kp = iter * BK;
            const int k2 = kp >> 8;
            const int c0 = kp & 255;
            const int g = c0 >> 6;
            const int ky = k2 / 3 - 1;
            const int kx = k2 - (k2 / 3) * 3 - 1;
            const float2* offp = g_off + (((size_t)(b * 36 + g * 9 + k2)) << 12) + hwbase;
            const float* xcb = xb + ((size_t)c0 << 12);
            float* bst = sBf + s * B_ST_F;

#pragma unroll
            for (int p2 = 0; p2 < 2; p2++) {
                const int pix = ptid + p2 * 64;
                const int hw = hwbase + pix;
                const int h = hw >> 6;
                const int w = hw & 63;
                const float2 of = __ldg(offp + pix);

                const float py = (float)(h + ky) + of.x;
                const float px = (float)(w + kx) + of.y;
                const float fy = floorf(py), fx = floorf(px);
                const int y0 = (int)fy, x0i = (int)fx;
                const float wy = py - fy, wx = px - fx;

                float w00 = (1.f - wy) * (1.f - wx);
                float w01 = (1.f - wy) * wx;
                float w10 = wy * (1.f - wx);
                float w11 = wy * wx;
                const bool vy0 = (y0 >= 0) & (y0 < Hn);
                const bool vy1 = (y0 + 1 >= 0) & (y0 + 1 < Hn);
                const bool vx0 = (x0i >= 0) & (x0i < Wn);
                const bool vx1 = (x0i + 1 >= 0) & (x0i + 1 < Wn);
                w00 = (vy0 & vx0) ? w00 : 0.f;
                w01 = (vy0 & vx1) ? w01 : 0.f;
                w10 = (vy1 & vx0) ? w10 : 0.f;
                w11 = (vy1 & vx1) ? w11 : 0.f;

                const int yc0 = min(max(y0, 0), Hn - 1);
                const int yc1 = min(max(y0 + 1, 0), Hn - 1);
                const int xc0 = min(max(x0i, 0), Wn - 1);
                const int xc1 = min(max(x0i + 1, 0), Wn - 1);
                const int i00 = yc0 * 64 + xc0;
                const int i01 = yc0 * 64 + xc1;
                const int i10 = yc1 * 64 + xc0;
                const int i11 = yc1 * 64 + xc1;

#pragma unroll
                for (int cc = 0; cc < 16; cc += 4) {
                    float t0[4], t1[4], t2[4], t3[4];
#pragma unroll
                    for (int j = 0; j < 4; j++) {
                        const float* xc = xcb + ((size_t)(cc + j) << 12);
                        t0[j] = __ldg(xc + i00);
                        t1[j] = __ldg(xc + i01);
                        t2[j] = __ldg(xc + i10);
                        t3[j] = __ldg(xc + i11);
                    }
#pragma unroll
                    for (int j = 0; j < 4; j++) {
                        const float v = w00 * t0[j] + w01 * t1[j]
                                      + w10 * t2[j] + w11 * t3[j];
                        bst[(cc + j) * 136 + pix] = to_tf32(v);
                    }
                }
            }
            __syncwarp();
            if (lane == 0) MBAR_ARRIVE(fullb + s * 8);
        }
        return;
    }

    // ===================== CONSUMER (8 warps, 256 threads) =================
    const int wid = tid >> 5;
    const int g4 = lane >> 2;
    const int l4 = lane & 3;
    const int wm = wid & 3;
    const int wn = wid >> 2;

    auto load_a = [&](int iter, int s) {
        const float4* srcA = (const float4*)g_A + (size_t)iter * 1024;
        const uint32_t dA = sA_u + (uint32_t)s * (A_ST_F * 4);
#pragma unroll
        for (int j = 0; j < 4; j++) {
            const int idx = j * 256 + tid;
            CP16(dA + idx * 16, srcA + idx);
        }
        CP_COMMIT();
    };
    load_a(0, 0);
    load_a(1, 1);
    load_a(2, 2);

    float acc[4][8][4];
#pragma unroll
    for (int i = 0; i < 4; i++)
#pragma unroll
        for (int j = 0; j < 8; j++)
#pragma unroll
            for (int q = 0; q < 4; q++) acc[i][j][q] = 0.f;

    int fph[3] = {0, 0, 0};

    for (int iter = 0; iter < ITERS; iter++) {
        const int s = iter % 3;
        CP_WAIT2();
        BAR_CONS();                                  // A(s) visible to all consumers
        mbar_wait(fullb + s * 8, (uint32_t)fph[s]); fph[s] ^= 1;   // B(s) ready

        const uint32_t aS = sA_u + (uint32_t)s * (A_ST_F * 4);
        const float* bS = sBf + s * B_ST_F;
#pragma unroll
        for (int k8 = 0; k8 < 2; k8++) {
            uint32_t af[4][4];
#pragma unroll
            for (int i = 0; i < 4; i++) {
                const uint32_t addr = aS + (((k8 * 16 + wm * 4 + i) * 32 + lane) << 4);
                asm volatile("ld.shared.v4.b32 {%0,%1,%2,%3}, [%4];"
                             : "=r"(af[i][0]), "=r"(af[i][1]), "=r"(af[i][2]), "=r"(af[i][3])
                             : "r"(addr));
            }
            uint32_t bf[8][2];
            const int r0 = k8 * 8 + l4;
            const float* bp = bS + wn * 64 + g4;
#pragma unroll
            for (int j = 0; j < 8; j++) {
                bf[j][0] = __float_as_uint(bp[r0 * 136 + j * 8]);
                bf[j][1] = __float_as_uint(bp[(r0 + 4) * 136 + j * 8]);
            }
#pragma unroll
            for (int i = 0; i < 4; i++)
#pragma unroll
                for (int j = 0; j < 8; j++)
                    mma_tf32(acc[i][j], af[i], bf[j]);
        }
        __syncwarp();
        if (lane == 0) MBAR_ARRIVE(emptyb + s * 8);  // this warp done with B(s)
        BAR_CONS();                                  // all consumers done with A(s)

        if (iter + 3 < ITERS) load_a(iter + 3, s);
        else CP_COMMIT();                            // keep wait_group accounting
    }

    // ---- epilogue: C -> out[b][o][hw] -------------------------------------
    const int hw0 = hwbase + wn * 64 + l4 * 2;
#pragma unroll
    for (int i = 0; i < 4; i++) {
        const int o0 = wm * 64 + i * 16 + g4;
        float* p0 = out + (((size_t)b * On + o0) << 12) + hw0;
        float* p1 = out + (((size_t)b * On + o0 + 8) << 12) + hw0;
#pragma unroll
        for (int j = 0; j < 8; j++) {
            *(float2*)(p0 + j * 8) = make_float2(acc[i][j][0], acc[i][j][1]);
            *(float2*)(p1 + j * 8) = make_float2(acc[i][j][2], acc[i][j][3]);
        }
    }
}

// ---------------------------------------------------------------------------
// GroupNorm statistics (one block per (b, group), contiguous 32768 floats)
// ---------------------------------------------------------------------------
__global__ void gn_stats_kernel(const float* __restrict__ y)
{
    const int bgp = blockIdx.x;
    const float* p = y + (size_t)bgp * 32768;
    const int tid = threadIdx.x;

    float s = 0.f, sq = 0.f;
    for (int i = tid * 4; i < 32768; i += 256 * 4) {
        float4 v = *(const float4*)(p + i);
        s  += v.x + v.y + v.z + v.w;
        sq += v.x * v.x + v.y * v.y + v.z * v.z + v.w * v.w;
    }

    __shared__ float ss[256], ssq[256];
    ss[tid] = s; ssq[tid] = sq;
    __syncthreads();
    for (int st = 128; st > 0; st >>= 1) {
        if (tid < st) { ss[tid] += ss[tid + st]; ssq[tid] += ssq[tid + st]; }
        __syncthreads();
    }
    if (tid == 0) {
        const float inv = 1.f / 32768.f;
        const float mu = ss[0] * inv;
        const float var = ssq[0] * inv - mu * mu;
        g_stats[bgp * 2 + 0] = mu;
        g_stats[bgp * 2 + 1] = rsqrtf(var + 1e-5f);
    }
}

// ---------------------------------------------------------------------------
// GroupNorm apply + ReLU (in place)
// ---------------------------------------------------------------------------
__global__ void gn_apply_kernel(float* __restrict__ y,
                                const float* __restrict__ gamma,
                                const float* __restrict__ beta)
{
    const int i = blockIdx.x * blockDim.x + threadIdx.x;
    const int e = i * 4;
    if (e >= Bn * On * HW) return;
    const int bgp = e >> 15;
    const int o = (e >> 12) & 255;
    const float mu = g_stats[bgp * 2 + 0];
    const float rs = g_stats[bgp * 2 + 1];
    const float ga = gamma[o] * rs;
    const float be = beta[o] - mu * ga;
    float4 v = *(float4*)(y + e);
    v.x = fmaxf(fmaf(v.x, ga, be), 0.f);
    v.y = fmaxf(fmaf(v.y, ga, be), 0.f);
    v.z = fmaxf(fmaf(v.z, ga, be), 0.f);
    v.w = fmaxf(fmaf(v.w, ga, be), 0.f);
    *(float4*)(y + e) = v;
}

// ---------------------------------------------------------------------------
extern "C" void kernel_launch(void* const* d_in, const int* in_sizes, int n_in,
                              void* d_out, int out_size)
{
    const float* x        = (const float*)d_in[0];
    const float* x_off    = (const float*)d_in[1];
    const float* w_offset = (const float*)d_in[2];
    const float* w_deform = (const float*)d_in[3];
    const float* gamma    = (const float*)d_in[4];
    const float* beta     = (const float*)d_in[5];
    float* out = (float*)d_out;

    (void)in_sizes; (void)n_in; (void)out_size;

    cudaFuncSetAttribute(gemm_kernel, cudaFuncAttributeMaxDynamicSharedMemorySize, GEMM_SMEM);

    prep_off_kernel<<<Bn * 36 * HW / 256, 256>>>(x_off, w_offset);
    prep_a_kernel<<<NK8 * 16 * 32 / 256, 256>>>(w_deform);
    gemm_kernel<<<NDIM / BN, 320, GEMM_SMEM>>>(x, out);
    gn_stats_kernel<<<256, 256>>>(out);
    gn_apply_kernel<<<(Bn * On * HW / 4 + 255) / 256, 256>>>(out, gamma, beta);
}

// round 6
// speedup vs baseline: 1.4595x; 1.4476x over previous
#include <cuda_runtime.h>
#include <cuda_fp16.h>
#include <cstdint>

// ---------------------------------------------------------------------------
// FeatureAlign: offset conv (1x1) -> deformable conv v1 -> GroupNorm -> ReLU
// sm_100 plain target: fp16 mma.sync (m16n8k16) + cp.async + mbarrier.
//
// Fused warp-specialized GEMM:
//   - 8 consumer warps: 3-stage fp16 mma GEMM (BM=256, BN=128, BK=16/k16)
//   - 4 producer warps: bilinear gather from NHWC-transposed x (float4 taps)
//   - K permuted: k' = k2*256 + c  (each BK=16 slice = one (g,k2), 16 chans)
// Prep kernels: x NCHW->NHWC transpose; offset 1x1 conv table; fp16
// fragment-ordered weights. GroupNorm stats + apply/ReLU on d_out.
// ---------------------------------------------------------------------------

#define Bn 8
#define Cn 256
#define On 256
#define Hn 64
#define Wn 64
#define HW 4096
#define K2 9
#define KDIM 2304
#define NDIM 32768

#define BM 256
#define BN 128
#define BK 16
#define ITERS (KDIM / BK)        // 144

__device__ float  g_xt[(size_t)Bn * HW * Cn];      // NHWC x (33.5 MB)
__device__ float2 g_off[(size_t)Bn * 36 * HW];     // [b][g*9+k2][hw] (9.4 MB)
__device__ uint4  g_Ah[(size_t)ITERS * 16 * 32];   // fp16 frag-ordered W (1.2 MB)
__device__ float  g_stats[256 * 2];

// ------------------------------ helpers ------------------------------------
__device__ __forceinline__ uint32_t smem_u32(const void* p) {
    uint32_t a;
    asm("{ .reg .u64 t; cvta.to.shared.u64 t, %1; cvt.u32.u64 %0, t; }" : "=r"(a) : "l"(p));
    return a;
}
__device__ __forceinline__ uint32_t pack_h2(float lo, float hi) {
    __half2 h = __floats2half2_rn(lo, hi);
    return *reinterpret_cast<uint32_t*>(&h);
}
#define CP16(dst_u32, src_ptr) \
    asm volatile("cp.async.cg.shared.global [%0], [%1], 16;" :: "r"(dst_u32), "l"(src_ptr) : "memory")
#define CP_COMMIT() asm volatile("cp.async.commit_group;" ::: "memory")
#define CP_WAIT2()  asm volatile("cp.async.wait_group 2;" ::: "memory")

#define MBAR_INIT(addr, cnt) \
    asm volatile("mbarrier.init.shared.b64 [%0], %1;" :: "r"(addr), "r"(cnt) : "memory")
#define MBAR_ARRIVE(addr) \
    asm volatile("mbarrier.arrive.shared.b64 _, [%0];" :: "r"(addr) : "memory")

__device__ __forceinline__ void mbar_wait(uint32_t mbar, uint32_t parity) {
    asm volatile(
        "{\n\t"
        ".reg .pred P;\n\t"
        "WL_%=:\n\t"
        "mbarrier.try_wait.parity.acquire.cta.shared::cta.b64 P, [%0], %1, 0x989680;\n\t"
        "@P bra.uni WD_%=;\n\t"
        "bra.uni WL_%=;\n\t"
        "WD_%=:\n\t"
        "}"
        :: "r"(mbar), "r"(parity) : "memory");
}

#define BAR_CONS() asm volatile("bar.sync 1, 256;" ::: "memory")

__device__ __forceinline__ void mma_f16(float* c, uint32_t a0, uint32_t a1,
                                        uint32_t a2, uint32_t a3,
                                        uint32_t b0, uint32_t b1) {
    asm volatile(
        "mma.sync.aligned.m16n8k16.row.col.f32.f16.f16.f32 "
        "{%0,%1,%2,%3}, {%4,%5,%6,%7}, {%8,%9}, {%0,%1,%2,%3};"
        : "+f"(c[0]), "+f"(c[1]), "+f"(c[2]), "+f"(c[3])
        : "r"(a0), "r"(a1), "r"(a2), "r"(a3), "r"(b0), "r"(b1));
}

// ---------------------------------------------------------------------------
// transpose: x [b][c][hw] -> g_xt [b][hw][c]
// grid (128, 8, 8), block (32, 8); 32x32 tiles via smem
// ---------------------------------------------------------------------------
__global__ void transpose_kernel(const float* __restrict__ x)
{
    __shared__ float tile[32][33];
    const int hw0 = blockIdx.x * 32;
    const int c0 = blockIdx.y * 32;
    const int b = blockIdx.z;
    const int tx = threadIdx.x;
    const int ty = threadIdx.y;

#pragma unroll
    for (int i = 0; i < 4; i++)
        tile[ty + i * 8][tx] = x[(((size_t)b * Cn + c0 + ty + i * 8) << 12) + hw0 + tx];
    __syncthreads();
#pragma unroll
    for (int i = 0; i < 4; i++)
        g_xt[(((size_t)b << 12) + hw0 + ty + i * 8) * Cn + c0 + tx] = tile[tx][ty + i * 8];
}

// ---------------------------------------------------------------------------
// prep_off: offset 1x1 conv -> g_off[b][g*9+k2][hw] = (offy, offx)
// ---------------------------------------------------------------------------
__global__ void prep_off_kernel(const float* __restrict__ x_off,
                                const float* __restrict__ w_offset)
{
    const int idx = blockIdx.x * 256 + threadIdx.x;    // < 1179648
    const int hw = idx & 4095;
    const int t = idx >> 12;                           // b*36 + gk
    const int b = t / 36;
    const int gk = t - b * 36;
    const int g = gk / 9;
    const int k2 = gk - g * 9;

    const float* xo = x_off + (size_t)b * 4 * HW + hw;
    const float o0 = __ldg(xo), o1 = __ldg(xo + HW);
    const float o2 = __ldg(xo + 2 * HW), o3 = __ldg(xo + 3 * HW);
    const float* wo = w_offset + (g * 18 + k2 * 2) * 4;
    const float offy = wo[0] * o0 + wo[1] * o1 + wo[2] * o2 + wo[3] * o3;
    const float offx = wo[4] * o0 + wo[5] * o1 + wo[6] * o2 + wo[7] * o3;
    g_off[idx] = make_float2(offy, offx);
}

// ---------------------------------------------------------------------------
// prep_a: weights -> fp16, m16n8k16 fragment order, k'-permuted (k'=k2*256+c)
// g_Ah[it][mt][lane] = {a0,a1,a2,a3}
// ---------------------------------------------------------------------------
__global__ void prep_a_kernel(const float* __restrict__ wd)   // [256][2304]
{
    const int idx = blockIdx.x * 256 + threadIdx.x;           // < 73728
    const int lane = idx & 31;
    const int mt = (idx >> 5) & 15;
    const int it = idx >> 9;                                   // 0..143
    const int r0 = mt * 16 + (lane >> 2);
    const int r1 = r0 + 8;
    const int k0 = it * 16 + (lane & 3) * 2;

    auto src = [](int kp) { return (kp & 255) * 9 + (kp >> 8); };
    const float* w0 = wd + (size_t)r0 * KDIM;
    const float* w1 = wd + (size_t)r1 * KDIM;
    uint4 v;
    v.x = pack_h2(w0[src(k0)],     w0[src(k0 + 1)]);
    v.y = pack_h2(w1[src(k0)],     w1[src(k0 + 1)]);
    v.z = pack_h2(w0[src(k0 + 8)], w0[src(k0 + 9)]);
    v.w = pack_h2(w1[src(k0 + 8)], w1[src(k0 + 9)]);
    g_Ah[idx] = v;
}

// ---------------------------------------------------------------------------
// Fused sample+GEMM, warp-specialized.
// grid = 256 n-tiles, block = 384: wid 0..7 consumers, wid 8..11 producers.
// smem: A stages 3 x 8192B (16 mt x 32 lane x uint4) | B stages 3 x 4096B
//       (128 pix x 16 fp16)
// ---------------------------------------------------------------------------
#define A_ST_B 8192
#define B_ST_B 4096
#define GEMM_SMEM (3 * A_ST_B + 3 * B_ST_B)

__global__ void __launch_bounds__(384, 1) gemm_kernel(float* __restrict__ out)
{
    extern __shared__ char smemc[];
    __shared__ uint64_t mbar[6];       // full[0..2], empty[3..5]
    const uint32_t sA_u = smem_u32(smemc);
    const uint32_t sB_u = sA_u + 3 * A_ST_B;
    const uint32_t fullb = smem_u32(&mbar[0]);
    const uint32_t emptyb = smem_u32(&mbar[3]);

    const int tid = threadIdx.x;
    const int lane = tid & 31;
    const int n0 = blockIdx.x * BN;
    const int b = n0 >> 12;
    const int hwbase = n0 & 4095;

    if (tid == 0) {
#pragma unroll
        for (int s = 0; s < 3; s++) {
            MBAR_INIT(fullb + s * 8, 4u);    // 4 producer warps
            MBAR_INIT(emptyb + s * 8, 8u);   // 8 consumer warps
        }
    }
    __syncthreads();

    if (tid >= 256) {
        // =================== PRODUCER (4 warps, 128 threads) ===============
        const int pwid = (tid >> 5) - 8;          // 0..3
        const int pixg = lane >> 2;               // 0..7
        const int quad = lane & 3;                // 0..3 (4 channels each)
        const float* xq_base = g_xt + ((size_t)b << 20) + quad * 4;
        int eph[3] = {1, 1, 1};
        float4 wv[4];
        int idx[4][4];

        for (int iter = 0; iter < ITERS; iter++) {
            const int s = iter % 3;
            mbar_wait(emptyb + s * 8, (uint32_t)eph[s]); eph[s] ^= 1;

            if ((iter & 3) == 0) {
                const int k2 = iter >> 4;
                const int g = (iter & 15) >> 2;
                const int ky = k2 / 3 - 1;
                const int kx = k2 - (k2 / 3) * 3 - 1;
                const float2* offp = g_off + (((size_t)(b * 36 + g * 9 + k2)) << 12) + hwbase;
#pragma unroll
                for (int grp = 0; grp < 4; grp++) {
                    const int pix = pwid * 32 + grp * 8 + pixg;
                    const int hw = hwbase + pix;
                    const int h = hw >> 6;
                    const int w = hw & 63;
                    const float2 of = __ldg(offp + pix);

                    const float py = (float)(h + ky) + of.x;
                    const float px = (float)(w + kx) + of.y;
                    const float fy = floorf(py), fx = floorf(px);
                    const int y0 = (int)fy, x0i = (int)fx;
                    const float wy = py - fy, wx = px - fx;

                    float w00 = (1.f - wy) * (1.f - wx);
                    float w01 = (1.f - wy) * wx;
                    float w10 = wy * (1.f - wx);
                    float w11 = wy * wx;
                    const bool vy0 = (y0 >= 0) & (y0 < Hn);
                    const bool vy1 = (y0 + 1 >= 0) & (y0 + 1 < Hn);
                    const bool vx0 = (x0i >= 0) & (x0i < Wn);
                    const bool vx1 = (x0i + 1 >= 0) & (x0i + 1 < Wn);
                    w00 = (vy0 & vx0) ? w00 : 0.f;
                    w01 = (vy0 & vx1) ? w01 : 0.f;
                    w10 = (vy1 & vx0) ? w10 : 0.f;
                    w11 = (vy1 & vx1) ? w11 : 0.f;

                    const int yc0 = min(max(y0, 0), Hn - 1);
                    const int yc1 = min(max(y0 + 1, 0), Hn - 1);
                    const int xc0 = min(max(x0i, 0), Wn - 1);
                    const int xc1 = min(max(x0i + 1, 0), Wn - 1);
                    idx[grp][0] = yc0 * 64 + xc0;
                    idx[grp][1] = yc0 * 64 + xc1;
                    idx[grp][2] = yc1 * 64 + xc0;
                    idx[grp][3] = yc1 * 64 + xc1;
                    wv[grp] = make_float4(w00, w01, w10, w11);
                }
            }

            const int c0 = (iter & 15) * 16;
            const float* xq = xq_base + c0;
            float4 t[4][4];
#pragma unroll
            for (int grp = 0; grp < 4; grp++)
#pragma unroll
                for (int tp = 0; tp < 4; tp++)
                    t[grp][tp] = *(const float4*)(xq + (size_t)idx[grp][tp] * Cn);

            const uint32_t bst = sB_u + (uint32_t)s * B_ST_B;
#pragma unroll
            for (int grp = 0; grp < 4; grp++) {
                const float4 wq = wv[grp];
                const float vx = wq.x * t[grp][0].x + wq.y * t[grp][1].x
                               + wq.z * t[grp][2].x + wq.w * t[grp][3].x;
                const float vy = wq.x * t[grp][0].y + wq.y * t[grp][1].y
                               + wq.z * t[grp][2].y + wq.w * t[grp][3].y;
                const float vz = wq.x * t[grp][0].z + wq.y * t[grp][1].z
                               + wq.z * t[grp][2].z + wq.w * t[grp][3].z;
                const float vw = wq.x * t[grp][0].w + wq.y * t[grp][1].w
                               + wq.z * t[grp][2].w + wq.w * t[grp][3].w;
                const uint32_t u0 = pack_h2(vx, vy);
                const uint32_t u1 = pack_h2(vz, vw);
                const int pix = pwid * 32 + grp * 8 + pixg;
                asm volatile("st.shared.v2.b32 [%0], {%1,%2};"
                             :: "r"(bst + (uint32_t)(pix * 32 + quad * 8)), "r"(u0), "r"(u1)
                             : "memory");
            }
            __syncwarp();
            if (lane == 0) MBAR_ARRIVE(fullb + s * 8);
        }
        return;
    }

    // ===================== CONSUMER (8 warps, 256 threads) =================
    const int wid = tid >> 5;
    const int g4 = lane >> 2;
    const int l4 = lane & 3;
    const int wm = wid & 3;
    const int wn = wid >> 2;

    auto load_a = [&](int iter, int s) {
        const uint4* srcA = g_Ah + (size_t)iter * 512;
        const uint32_t dA = sA_u + (uint32_t)s * A_ST_B;
#pragma unroll
        for (int j = 0; j < 2; j++) {
            const int i2 = j * 256 + tid;
            CP16(dA + i2 * 16, srcA + i2);
        }
        CP_COMMIT();
    };
    load_a(0, 0);
    load_a(1, 1);
    load_a(2, 2);

    float acc[4][8][4];
#pragma unroll
    for (int i = 0; i < 4; i++)
#pragma unroll
        for (int j = 0; j < 8; j++)
#pragma unroll
            for (int q = 0; q < 4; q++) acc[i][j][q] = 0.f;

    int fph[3] = {0, 0, 0};

    for (int iter = 0; iter < ITERS; iter++) {
        const int s = iter % 3;
        CP_WAIT2();
        BAR_CONS();                                  // A(s) visible
        mbar_wait(fullb + s * 8, (uint32_t)fph[s]); fph[s] ^= 1;   // B(s) ready

        const uint32_t aS = sA_u + (uint32_t)s * A_ST_B;
        const uint32_t bS = sB_u + (uint32_t)s * B_ST_B;

        uint32_t bf[8][2];
#pragma unroll
        for (int j = 0; j < 8; j++) {
            const uint32_t baddr = bS + (uint32_t)((wn * 64 + j * 8 + g4) * 32 + l4 * 4);
            asm volatile("ld.shared.b32 %0, [%1];" : "=r"(bf[j][0]) : "r"(baddr));
            asm volatile("ld.shared.b32 %0, [%1];" : "=r"(bf[j][1]) : "r"(baddr + 16));
        }
#pragma unroll
        for (int i = 0; i < 4; i++) {
            uint32_t a0, a1, a2, a3;
            const uint32_t aaddr = aS + (uint32_t)(((wm * 4 + i) * 32 + lane) * 16);
            asm volatile("ld.shared.v4.b32 {%0,%1,%2,%3}, [%4];"
                         : "=r"(a0), "=r"(a1), "=r"(a2), "=r"(a3) : "r"(aaddr));
#pragma unroll
            for (int j = 0; j < 8; j++)
                mma_f16(acc[i][j], a0, a1, a2, a3, bf[j][0], bf[j][1]);
        }
        __syncwarp();
        if (lane == 0) MBAR_ARRIVE(emptyb + s * 8);  // this warp done with B(s)
        BAR_CONS();                                  // all consumers done with A(s)

        if (iter + 3 < ITERS) load_a(iter + 3, s);
        else CP_COMMIT();                            // keep wait_group accounting
    }

    // ---- epilogue: C -> out[b][o][hw] -------------------------------------
    const int hw0 = hwbase + wn * 64 + l4 * 2;
#pragma unroll
    for (int i = 0; i < 4; i++) {
        const int o0 = wm * 64 + i * 16 + g4;
        float* p0 = out + (((size_t)b * On + o0) << 12) + hw0;
        float* p1 = out + (((size_t)b * On + o0 + 8) << 12) + hw0;
#pragma unroll
        for (int j = 0; j < 8; j++) {
            *(float2*)(p0 + j * 8) = make_float2(acc[i][j][0], acc[i][j][1]);
            *(float2*)(p1 + j * 8) = make_float2(acc[i][j][2], acc[i][j][3]);
        }
    }
}

// ---------------------------------------------------------------------------
// GroupNorm statistics (one block per (b, group), contiguous 32768 floats)
// ---------------------------------------------------------------------------
__global__ void gn_stats_kernel(const float* __restrict__ y)
{
    const int bgp = blockIdx.x;
    const float* p = y + (size_t)bgp * 32768;
    const int tid = threadIdx.x;

    float s = 0.f, sq = 0.f;
    for (int i = tid * 4; i < 32768; i += 256 * 4) {
        float4 v = *(const float4*)(p + i);
        s  += v.x + v.y + v.z + v.w;
        sq += v.x * v.x + v.y * v.y + v.z * v.z + v.w * v.w;
    }

    __shared__ float ss[256], ssq[256];
    ss[tid] = s; ssq[tid] = sq;
    __syncthreads();
    for (int st = 128; st > 0; st >>= 1) {
        if (tid < st) { ss[tid] += ss[tid + st]; ssq[tid] += ssq[tid + st]; }
        __syncthreads();
    }
    if (tid == 0) {
        const float inv = 1.f / 32768.f;
        const float mu = ss[0] * inv;
        const float var = ssq[0] * inv - mu * mu;
        g_stats[bgp * 2 + 0] = mu;
        g_stats[bgp * 2 + 1] = rsqrtf(var + 1e-5f);
    }
}

// ---------------------------------------------------------------------------
// GroupNorm apply + ReLU (in place)
// ---------------------------------------------------------------------------
__global__ void gn_apply_kernel(float* __restrict__ y,
                                const float* __restrict__ gamma,
                                const float* __restrict__ beta)
{
    const int i = blockIdx.x * blockDim.x + threadIdx.x;
    const int e = i * 4;
    if (e >= Bn * On * HW) return;
    const int bgp = e >> 15;
    const int o = (e >> 12) & 255;
    const float mu = g_stats[bgp * 2 + 0];
    const float rs = g_stats[bgp * 2 + 1];
    const float ga = gamma[o] * rs;
    const float be = beta[o] - mu * ga;
    float4 v = *(float4*)(y + e);
    v.x = fmaxf(fmaf(v.x, ga, be), 0.f);
    v.y = fmaxf(fmaf(v.y, ga, be), 0.f);
    v.z = fmaxf(fmaf(v.z, ga, be), 0.f);
    v.w = fmaxf(fmaf(v.w, ga, be), 0.f);
    *(float4*)(y + e) = v;
}

// ---------------------------------------------------------------------------
extern "C" void kernel_launch(void* const* d_in, const int* in_sizes, int n_in,
                              void* d_out, int out_size)
{
    const float* x        = (const float*)d_in[0];
    const float* x_off    = (const float*)d_in[1];
    const float* w_offset = (const float*)d_in[2];
    const float* w_deform = (const float*)d_in[3];
    const float* gamma    = (const float*)d_in[4];
    const float* beta     = (const float*)d_in[5];
    float* out = (float*)d_out;

    (void)in_sizes; (void)n_in; (void)out_size;

    cudaFuncSetAttribute(gemm_kernel, cudaFuncAttributeMaxDynamicSharedMemorySize, GEMM_SMEM);

    transpose_kernel<<<dim3(HW / 32, Cn / 32, Bn), dim3(32, 8)>>>(x);
    prep_off_kernel<<<Bn * 36 * HW / 256, 256>>>(x_off, w_offset);
    prep_a_kernel<<<ITERS * 16 * 32 / 256, 256>>>(w_deform);
    gemm_kernel<<<NDIM / BN, 384, GEMM_SMEM>>>(out);
    gn_stats_kernel<<<256, 256>>>(out);
    gn_apply_kernel<<<(Bn * On * HW / 4 + 255) / 256, 256>>>(out, gamma, beta);
}

// round 7
// speedup vs baseline: 1.4762x; 1.0114x over previous
#include <cuda_runtime.h>
#include <cuda_fp16.h>
#include <cstdint>

// ---------------------------------------------------------------------------
// FeatureAlign: offset conv (1x1) -> deformable conv v1 -> GroupNorm -> ReLU
// sm_100 plain target: fp16 mma.sync (m16n8k16) + cp.async + mbarrier.
//
// Fused warp-specialized GEMM:
//   - 8 consumer warps: fp16 mma GEMM (BM=256, BN=128, BK=16), 6-stage
//     warp-private A pipeline (no CTA barriers in the mainloop)
//   - 4 producer warps: bilinear gather from NHWC-transposed x, 3-stage B
//   - B smem stored as per-(pix,l4) uint2 fragments -> conflict-free LDS.64
//   - K permuted: k' = k2*256 + c  (each BK=16 slice = one (g,k2), 16 chans)
// ---------------------------------------------------------------------------

#define Bn 8
#define Cn 256
#define On 256
#define Hn 64
#define Wn 64
#define HW 4096
#define K2 9
#define KDIM 2304
#define NDIM 32768

#define BM 256
#define BN 128
#define BK 16
#define ITERS (KDIM / BK)        // 144

__device__ float  g_xt[(size_t)Bn * HW * Cn];      // NHWC x (33.5 MB)
__device__ float2 g_off[(size_t)Bn * 36 * HW];     // [b][g*9+k2][hw] (9.4 MB)
__device__ uint4  g_Ah[(size_t)ITERS * 16 * 32];   // fp16 frag-ordered W (1.2 MB)
__device__ float  g_stats[256 * 2];

// ------------------------------ helpers ------------------------------------
__device__ __forceinline__ uint32_t smem_u32(const void* p) {
    uint32_t a;
    asm("{ .reg .u64 t; cvta.to.shared.u64 t, %1; cvt.u32.u64 %0, t; }" : "=r"(a) : "l"(p));
    return a;
}
__device__ __forceinline__ uint32_t pack_h2(float lo, float hi) {
    __half2 h = __floats2half2_rn(lo, hi);
    return *reinterpret_cast<uint32_t*>(&h);
}
#define CP16(dst_u32, src_ptr) \
    asm volatile("cp.async.cg.shared.global [%0], [%1], 16;" :: "r"(dst_u32), "l"(src_ptr) : "memory")
#define CP_COMMIT() asm volatile("cp.async.commit_group;" ::: "memory")
#define CP_WAIT5()  asm volatile("cp.async.wait_group 5;" ::: "memory")

#define MBAR_INIT(addr, cnt) \
    asm volatile("mbarrier.init.shared.b64 [%0], %1;" :: "r"(addr), "r"(cnt) : "memory")
#define MBAR_ARRIVE(addr) \
    asm volatile("mbarrier.arrive.shared.b64 _, [%0];" :: "r"(addr) : "memory")

__device__ __forceinline__ void mbar_wait(uint32_t mbar, uint32_t parity) {
    asm volatile(
        "{\n\t"
        ".reg .pred P;\n\t"
        "WL_%=:\n\t"
        "mbarrier.try_wait.parity.acquire.cta.shared::cta.b64 P, [%0], %1, 0x989680;\n\t"
        "@P bra.uni WD_%=;\n\t"
        "bra.uni WL_%=;\n\t"
        "WD_%=:\n\t"
        "}"
        :: "r"(mbar), "r"(parity) : "memory");
}

__device__ __forceinline__ void mma_f16(float* c, uint32_t a0, uint32_t a1,
                                        uint32_t a2, uint32_t a3,
                                        uint32_t b0, uint32_t b1) {
    asm volatile(
        "mma.sync.aligned.m16n8k16.row.col.f32.f16.f16.f32 "
        "{%0,%1,%2,%3}, {%4,%5,%6,%7}, {%8,%9}, {%0,%1,%2,%3};"
        : "+f"(c[0]), "+f"(c[1]), "+f"(c[2]), "+f"(c[3])
        : "r"(a0), "r"(a1), "r"(a2), "r"(a3), "r"(b0), "r"(b1));
}

// ---------------------------------------------------------------------------
// transpose: x [b][c][hw] -> g_xt [b][hw][c]
// ---------------------------------------------------------------------------
__global__ void transpose_kernel(const float* __restrict__ x)
{
    __shared__ float tile[32][33];
    const int hw0 = blockIdx.x * 32;
    const int c0 = blockIdx.y * 32;
    const int b = blockIdx.z;
    const int tx = threadIdx.x;
    const int ty = threadIdx.y;

#pragma unroll
    for (int i = 0; i < 4; i++)
        tile[ty + i * 8][tx] = x[(((size_t)b * Cn + c0 + ty + i * 8) << 12) + hw0 + tx];
    __syncthreads();
#pragma unroll
    for (int i = 0; i < 4; i++)
        g_xt[(((size_t)b << 12) + hw0 + ty + i * 8) * Cn + c0 + tx] = tile[tx][ty + i * 8];
}

// ---------------------------------------------------------------------------
// prep_off: offset 1x1 conv -> g_off[b][g*9+k2][hw] = (offy, offx)
// ---------------------------------------------------------------------------
__global__ void prep_off_kernel(const float* __restrict__ x_off,
                                const float* __restrict__ w_offset)
{
    const int idx = blockIdx.x * 256 + threadIdx.x;    // < 1179648
    const int hw = idx & 4095;
    const int t = idx >> 12;                           // b*36 + gk
    const int b = t / 36;
    const int gk = t - b * 36;
    const int g = gk / 9;
    const int k2 = gk - g * 9;

    const float* xo = x_off + (size_t)b * 4 * HW + hw;
    const float o0 = __ldg(xo), o1 = __ldg(xo + HW);
    const float o2 = __ldg(xo + 2 * HW), o3 = __ldg(xo + 3 * HW);
    const float* wo = w_offset + (g * 18 + k2 * 2) * 4;
    const float offy = wo[0] * o0 + wo[1] * o1 + wo[2] * o2 + wo[3] * o3;
    const float offx = wo[4] * o0 + wo[5] * o1 + wo[6] * o2 + wo[7] * o3;
    g_off[idx] = make_float2(offy, offx);
}

// ---------------------------------------------------------------------------
// prep_a: weights -> fp16, m16n8k16 fragment order, k'-permuted (k'=k2*256+c)
// ---------------------------------------------------------------------------
__global__ void prep_a_kernel(const float* __restrict__ wd)   // [256][2304]
{
    const int idx = blockIdx.x * 256 + threadIdx.x;           // < 73728
    const int lane = idx & 31;
    const int mt = (idx >> 5) & 15;
    const int it = idx >> 9;                                   // 0..143
    const int r0 = mt * 16 + (lane >> 2);
    const int r1 = r0 + 8;
    const int k0 = it * 16 + (lane & 3) * 2;

    auto src = [](int kp) { return (kp & 255) * 9 + (kp >> 8); };
    const float* w0 = wd + (size_t)r0 * KDIM;
    const float* w1 = wd + (size_t)r1 * KDIM;
    uint4 v;
    v.x = pack_h2(w0[src(k0)],     w0[src(k0 + 1)]);
    v.y = pack_h2(w1[src(k0)],     w1[src(k0 + 1)]);
    v.z = pack_h2(w0[src(k0 + 8)], w0[src(k0 + 9)]);
    v.w = pack_h2(w1[src(k0 + 8)], w1[src(k0 + 9)]);
    g_Ah[idx] = v;
}

// ---------------------------------------------------------------------------
// Fused sample+GEMM, warp-specialized.
// grid = 256 n-tiles, block = 384: wid 0..7 consumers, wid 8..11 producers.
// smem: A 6 stages x 2 wn-copies x 16 mt x 32 lane x uint4  (96 KB)
//       B 3 stages x 128 pix x 4 l4 x uint2                 (12 KB)
// ---------------------------------------------------------------------------
#define A_ST_B 16384                 // per stage (both wn copies)
#define B_ST_B 4096
#define GEMM_SMEM (6 * A_ST_B + 3 * B_ST_B)

__global__ void __launch_bounds__(384, 1) gemm_kernel(float* __restrict__ out)
{
    extern __shared__ char smemc[];
    __shared__ uint64_t mbar[6];       // full[0..2], empty[3..5]
    const uint32_t sA_u = smem_u32(smemc);
    const uint32_t sB_u = sA_u + 6 * A_ST_B;
    const uint32_t fullb = smem_u32(&mbar[0]);
    const uint32_t emptyb = smem_u32(&mbar[3]);

    const int tid = threadIdx.x;
    const int lane = tid & 31;
    const int n0 = blockIdx.x * BN;
    const int b = n0 >> 12;
    const int hwbase = n0 & 4095;

    if (tid == 0) {
#pragma unroll
        for (int s = 0; s < 3; s++) {
            MBAR_INIT(fullb + s * 8, 4u);    // 4 producer warps
            MBAR_INIT(emptyb + s * 8, 8u);   // 8 consumer warps
        }
    }
    __syncthreads();

    if (tid >= 256) {
        // =================== PRODUCER (4 warps, 128 threads) ===============
        const int pwid = (tid >> 5) - 8;          // 0..3
        const int pixg = lane >> 2;               // 0..7
        const int quad = lane & 3;                // 0..3 (4 channels each)
        const int l4a = (quad & 1) * 2;           // B-frag l4 slot for u0
        const int halfo = (quad >> 1) * 4;        // byte offset: first/second k-half
        const float* xq_base = g_xt + ((size_t)b << 20) + quad * 4;
        int eph[3] = {1, 1, 1};
        float4 wv[4];
        int idx[4][4];

        for (int iter = 0; iter < ITERS; iter++) {
            const int s = iter % 3;
            mbar_wait(emptyb + s * 8, (uint32_t)eph[s]); eph[s] ^= 1;

            if ((iter & 3) == 0) {
                const int k2 = iter >> 4;
                const int g = (iter & 15) >> 2;
                const int ky = k2 / 3 - 1;
                const int kx = k2 - (k2 / 3) * 3 - 1;
                const float2* offp = g_off + (((size_t)(b * 36 + g * 9 + k2)) << 12) + hwbase;
#pragma unroll
                for (int grp = 0; grp < 4; grp++) {
                    const int pix = pwid * 32 + grp * 8 + pixg;
                    const int hw = hwbase + pix;
                    const int h = hw >> 6;
                    const int w = hw & 63;
                    const float2 of = __ldg(offp + pix);

                    const float py = (float)(h + ky) + of.x;
                    const float px = (float)(w + kx) + of.y;
                    const float fy = floorf(py), fx = floorf(px);
                    const int y0 = (int)fy, x0i = (int)fx;
                    const float wy = py - fy, wx = px - fx;

                    float w00 = (1.f - wy) * (1.f - wx);
                    float w01 = (1.f - wy) * wx;
                    float w10 = wy * (1.f - wx);
                    float w11 = wy * wx;
                    const bool vy0 = (y0 >= 0) & (y0 < Hn);
                    const bool vy1 = (y0 + 1 >= 0) & (y0 + 1 < Hn);
                    const bool vx0 = (x0i >= 0) & (x0i < Wn);
                    const bool vx1 = (x0i + 1 >= 0) & (x0i + 1 < Wn);
                    w00 = (vy0 & vx0) ? w00 : 0.f;
                    w01 = (vy0 & vx1) ? w01 : 0.f;
                    w10 = (vy1 & vx0) ? w10 : 0.f;
                    w11 = (vy1 & vx1) ? w11 : 0.f;

                    const int yc0 = min(max(y0, 0), Hn - 1);
                    const int yc1 = min(max(y0 + 1, 0), Hn - 1);
                    const int xc0 = min(max(x0i, 0), Wn - 1);
                    const int xc1 = min(max(x0i + 1, 0), Wn - 1);
                    idx[grp][0] = yc0 * 64 + xc0;
                    idx[grp][1] = yc0 * 64 + xc1;
                    idx[grp][2] = yc1 * 64 + xc0;
                    idx[grp][3] = yc1 * 64 + xc1;
                    wv[grp] = make_float4(w00, w01, w10, w11);
                }
            }

            const int c0 = (iter & 15) * 16;
            const float* xq = xq_base + c0;
            float4 t[4][4];
#pragma unroll
            for (int grp = 0; grp < 4; grp++)
#pragma unroll
                for (int tp = 0; tp < 4; tp++)
                    t[grp][tp] = *(const float4*)(xq + (size_t)idx[grp][tp] * Cn);

            const uint32_t bst = sB_u + (uint32_t)s * B_ST_B;
#pragma unroll
            for (int grp = 0; grp < 4; grp++) {
                const float4 wq = wv[grp];
                const float vx = wq.x * t[grp][0].x + wq.y * t[grp][1].x
                               + wq.z * t[grp][2].x + wq.w * t[grp][3].x;
                const float vy = wq.x * t[grp][0].y + wq.y * t[grp][1].y
                               + wq.z * t[grp][2].y + wq.w * t[grp][3].y;
                const float vz = wq.x * t[grp][0].z + wq.y * t[grp][1].z
                               + wq.z * t[grp][2].z + wq.w * t[grp][3].z;
                const float vw = wq.x * t[grp][0].w + wq.y * t[grp][1].w
                               + wq.z * t[grp][2].w + wq.w * t[grp][3].w;
                const uint32_t u0 = pack_h2(vx, vy);   // channels 4q, 4q+1
                const uint32_t u1 = pack_h2(vz, vw);   // channels 4q+2, 4q+3
                const int pix = pwid * 32 + grp * 8 + pixg;
                const uint32_t a0 = bst + (uint32_t)(pix * 32 + l4a * 8 + halfo);
                asm volatile("st.shared.b32 [%0], %1;" :: "r"(a0), "r"(u0) : "memory");
                asm volatile("st.shared.b32 [%0], %1;" :: "r"(a0 + 8), "r"(u1) : "memory");
            }
            __syncwarp();
            if (lane == 0) MBAR_ARRIVE(fullb + s * 8);
        }
        return;
    }

    // ===================== CONSUMER (8 warps, 256 threads) =================
    const int wid = tid >> 5;
    const int g4 = lane >> 2;
    const int l4 = lane & 3;
    const int wm = wid & 3;
    const int wn = wid >> 2;

    // warp-private A staging: this warp loads & reads only rows wm*4..wm*4+3
    // of its own wn-copy.
    auto load_a = [&](int iter, int s) {
        const uint4* srcA = g_Ah + (size_t)iter * 512 + (wm * 4) * 32 + lane;
        const uint32_t dA = sA_u + (uint32_t)s * A_ST_B + (uint32_t)wn * 8192
                          + (uint32_t)((wm * 4) * 32 + lane) * 16;
#pragma unroll
        for (int i = 0; i < 4; i++)
            CP16(dA + i * 512, srcA + i * 32);
        CP_COMMIT();
    };
#pragma unroll
    for (int p = 0; p < 6; p++) load_a(p, p);

    float acc[4][8][4];
#pragma unroll
    for (int i = 0; i < 4; i++)
#pragma unroll
        for (int j = 0; j < 8; j++)
#pragma unroll
            for (int q = 0; q < 4; q++) acc[i][j][q] = 0.f;

    int fph[3] = {0, 0, 0};

    for (int iter = 0; iter < ITERS; iter++) {
        const int sb = iter % 3;
        const int sa = iter % 6;
        CP_WAIT5();                                  // own A(iter) landed
        __syncwarp();
        mbar_wait(fullb + sb * 8, (uint32_t)fph[sb]); fph[sb] ^= 1;   // B ready

        const uint32_t aS = sA_u + (uint32_t)sa * A_ST_B + (uint32_t)wn * 8192;
        const uint32_t bS = sB_u + (uint32_t)sb * B_ST_B;

        uint32_t bf[8][2];
#pragma unroll
        for (int j = 0; j < 8; j++) {
            const uint32_t baddr = bS + (uint32_t)(((wn * 64 + j * 8 + g4) * 4 + l4) * 8);
            asm volatile("ld.shared.v2.b32 {%0,%1}, [%2];"
                         : "=r"(bf[j][0]), "=r"(bf[j][1]) : "r"(baddr));
        }
#pragma unroll
        for (int i = 0; i < 4; i++) {
            uint32_t a0, a1, a2, a3;
            const uint32_t aaddr = aS + (uint32_t)(((wm * 4 + i) * 32 + lane) * 16);
            asm volatile("ld.shared.v4.b32 {%0,%1,%2,%3}, [%4];"
                         : "=r"(a0), "=r"(a1), "=r"(a2), "=r"(a3) : "r"(aaddr));
#pragma unroll
            for (int j = 0; j < 8; j++)
                mma_f16(acc[i][j], a0, a1, a2, a3, bf[j][0], bf[j][1]);
        }
        __syncwarp();
        if (lane == 0) MBAR_ARRIVE(emptyb + sb * 8); // done with B(sb)

        if (iter + 6 < ITERS) load_a(iter + 6, sa);
        else CP_COMMIT();                            // keep wait_group accounting
    }

    // ---- epilogue: C -> out[b][o][hw] -------------------------------------
    const int hw0 = hwbase + wn * 64 + l4 * 2;
#pragma unroll
    for (int i = 0; i < 4; i++) {
        const int o0 = wm * 64 + i * 16 + g4;
        float* p0 = out + (((size_t)b * On + o0) << 12) + hw0;
        float* p1 = out + (((size_t)b * On + o0 + 8) << 12) + hw0;
#pragma unroll
        for (int j = 0; j < 8; j++) {
            *(float2*)(p0 + j * 8) = make_float2(acc[i][j][0], acc[i][j][1]);
            *(float2*)(p1 + j * 8) = make_float2(acc[i][j][2], acc[i][j][3]);
        }
    }
}

// ---------------------------------------------------------------------------
// GroupNorm statistics (one block per (b, group), contiguous 32768 floats)
// ---------------------------------------------------------------------------
__global__ void gn_stats_kernel(const float* __restrict__ y)
{
    const int bgp = blockIdx.x;
    const float* p = y + (size_t)bgp * 32768;
    const int tid = threadIdx.x;

    float s = 0.f, sq = 0.f;
    for (int i = tid * 4; i < 32768; i += 256 * 4) {
        float4 v = *(const float4*)(p + i);
        s  += v.x + v.y + v.z + v.w;
        sq += v.x * v.x + v.y * v.y + v.z * v.z + v.w * v.w;
    }

    __shared__ float ss[256], ssq[256];
    ss[tid] = s; ssq[tid] = sq;
    __syncthreads();
    for (int st = 128; st > 0; st >>= 1) {
        if (tid < st) { ss[tid] += ss[tid + st]; ssq[tid] += ssq[tid + st]; }
        __syncthreads();
    }
    if (tid == 0) {
        const float inv = 1.f / 32768.f;
        const float mu = ss[0] * inv;
        const float var = ssq[0] * inv - mu * mu;
        g_stats[bgp * 2 + 0] = mu;
        g_stats[bgp * 2 + 1] = rsqrtf(var + 1e-5f);
    }
}

// ---------------------------------------------------------------------------
// GroupNorm apply + ReLU (in place)
// ---------------------------------------------------------------------------
__global__ void gn_apply_kernel(float* __restrict__ y,
                                const float* __restrict__ gamma,
                                const float* __restrict__ beta)
{
    const int i = blockIdx.x * blockDim.x + threadIdx.x;
    const int e = i * 4;
    if (e >= Bn * On * HW) return;
    const int bgp = e >> 15;
    const int o = (e >> 12) & 255;
    const float mu = g_stats[bgp * 2 + 0];
    const float rs = g_stats[bgp * 2 + 1];
    const float ga = gamma[o] * rs;
    const float be = beta[o] - mu * ga;
    float4 v = *(float4*)(y + e);
    v.x = fmaxf(fmaf(v.x, ga, be), 0.f);
    v.y = fmaxf(fmaf(v.y, ga, be), 0.f);
    v.z = fmaxf(fmaf(v.z, ga, be), 0.f);
    v.w = fmaxf(fmaf(v.w, ga, be), 0.f);
    *(float4*)(y + e) = v;
}

// ---------------------------------------------------------------------------
extern "C" void kernel_launch(void* const* d_in, const int* in_sizes, int n_in,
                              void* d_out, int out_size)
{
    const float* x        = (const float*)d_in[0];
    const float* x_off    = (const float*)d_in[1];
    const float* w_offset = (const float*)d_in[2];
    const float* w_deform = (const float*)d_in[3];
    const float* gamma    = (const float*)d_in[4];
    const float* beta     = (const float*)d_in[5];
    float* out = (float*)d_out;

    (void)in_sizes; (void)n_in; (void)out_size;

    cudaFuncSetAttribute(gemm_kernel, cudaFuncAttributeMaxDynamicSharedMemorySize, GEMM_SMEM);

    transpose_kernel<<<dim3(HW / 32, Cn / 32, Bn), dim3(32, 8)>>>(x);
    prep_off_kernel<<<Bn * 36 * HW / 256, 256>>>(x_off, w_offset);
    prep_a_kernel<<<ITERS * 16 * 32 / 256, 256>>>(w_deform);
    gemm_kernel<<<NDIM / BN, 384, GEMM_SMEM>>>(out);
    gn_stats_kernel<<<256, 256>>>(out);
    gn_apply_kernel<<<(Bn * On * HW / 4 + 255) / 256, 256>>>(out, gamma, beta);
}